// round 9
// baseline (speedup 1.0000x reference)
#include <cuda_runtime.h>
#include <cuda_fp16.h>
#include <cstdint>

#define BB 32
#define TT 512
#define DD 512
#define EE 8
#define HH 2048

// ---------------- device scratch (no cudaMalloc allowed) -------------------
__device__ __half g_h[(size_t)BB * TT * HH];      // h (relu'd)   64 MB
__device__ __half g_x[(size_t)BB * TT * DD];      // x as fp16    16 MB
__device__ __half g_W1t[(size_t)EE * HH * DD];    // W1^T fp16 [E][H][D] 16 MB
__device__ __half g_W2t[(size_t)EE * DD * HH];    // W2^T fp16 [E][D][H] 16 MB
__device__ float  g_part[BB * 8 * DD];
__device__ int    g_expert[BB];

// ---------------- helpers ---------------------------------------------------
__device__ __forceinline__ uint32_t smem_u32(const void* p) {
    uint32_t a;
    asm("{ .reg .u64 t; cvta.to.shared.u64 t, %1; cvt.u32.u64 %0, t; }" : "=r"(a) : "l"(p));
    return a;
}
#define SWZ(o) ((o) ^ ((((uint32_t)(o)) >> 3) & 0x70u))

__device__ __forceinline__ void cp_async16(uint32_t dst, const void* src) {
    asm volatile("cp.async.cg.shared.global [%0], [%1], 16;" :: "r"(dst), "l"(src));
}
__device__ __forceinline__ void cp_commit() {
    asm volatile("cp.async.commit_group;" ::: "memory");
}
__device__ __forceinline__ void cp_wait1() {
    asm volatile("cp.async.wait_group 1;" ::: "memory");
}
__device__ __forceinline__ void ldsm4(uint32_t* r, uint32_t addr) {
    asm volatile("ldmatrix.sync.aligned.m8n8.x4.shared.b16 {%0,%1,%2,%3}, [%4];"
                 : "=r"(r[0]), "=r"(r[1]), "=r"(r[2]), "=r"(r[3]) : "r"(addr));
}
__device__ __forceinline__ void mma16816(float* d, const uint32_t* a, uint32_t b0, uint32_t b1) {
    asm volatile("mma.sync.aligned.m16n8k16.row.col.f32.f16.f16.f32 "
                 "{%0,%1,%2,%3}, {%4,%5,%6,%7}, {%8,%9}, {%0,%1,%2,%3};"
                 : "+f"(d[0]), "+f"(d[1]), "+f"(d[2]), "+f"(d[3])
                 : "r"(a[0]), "r"(a[1]), "r"(a[2]), "r"(a[3]), "r"(b0), "r"(b1));
}

// ---------------- router (fused x -> fp16 convert + pooling) ----------------
__global__ void convert_pool(const float* __restrict__ x, __half2* __restrict__ xt,
                             float* __restrict__ part) {
    if (threadIdx.x == 0) cudaTriggerProgrammaticLaunchCompletion();
    int b = blockIdx.x, s = blockIdx.y, tid = threadIdx.x;   // tid: half2 index 0..255
    size_t base = ((size_t)b * TT + s * 64) * DD;
    float s0 = 0.f, s1 = 0.f;
    #pragma unroll 4
    for (int t = 0; t < 64; ++t) {
        float2 v = *reinterpret_cast<const float2*>(x + base + (size_t)t * DD + 2 * tid);
        s0 += v.x; s1 += v.y;
        xt[(base + (size_t)t * DD) / 2 + tid] = __floats2half2_rn(v.x, v.y);
    }
    float2 p; p.x = s0; p.y = s1;
    *reinterpret_cast<float2*>(part + ((size_t)b * 8 + s) * DD + 2 * tid) = p;
}

__global__ void router_final(const float* __restrict__ part,
                             const float* __restrict__ Wp,
                             const float* __restrict__ bp,
                             float* __restrict__ out_tail) {
    int b = blockIdx.x, tid = threadIdx.x;
    __shared__ float pooled[DD];
    __shared__ float logits[EE];

    for (int d = tid; d < DD; d += 256) {
        float s = 0.f;
        #pragma unroll
        for (int p = 0; p < 8; ++p) s += part[((size_t)b * 8 + p) * DD + d];
        pooled[d] = s * (1.0f / TT);
    }
    __syncthreads();

    int warp = tid >> 5, lane = tid & 31;
    if (warp < EE) {
        float s = 0.f;
        for (int d = lane; d < DD; d += 32) s += pooled[d] * Wp[(size_t)d * EE + warp];
        #pragma unroll
        for (int o = 16; o > 0; o >>= 1) s += __shfl_xor_sync(0xffffffffu, s, o);
        if (lane == 0) logits[warp] = s + bp[warp];
    }
    __syncthreads();

    if (tid == 0) {
        float m = logits[0]; int arg = 0;
        #pragma unroll
        for (int e = 1; e < EE; ++e) if (logits[e] > m) { m = logits[e]; arg = e; }
        float p[EE], sum = 0.f;
        #pragma unroll
        for (int e = 0; e < EE; ++e) { p[e] = __expf(logits[e] - m); sum += p[e]; }
        float inv = 1.0f / sum;
        #pragma unroll
        for (int e = 0; e < EE; ++e) out_tail[b * EE + e] = p[e] * inv;
        out_tail[BB * EE + b] = (float)arg;
        g_expert[b] = arg;
    }
}

// ---------------- fused weight transpose + fp16 rounding ---------------------
// W1 ([E][D][H] -> [E][H][D]) and W2 ([E][H][D] -> [E][D][H]) in one grid.
__global__ void transpose_both(const float* __restrict__ W1, __half* __restrict__ W1t,
                               const float* __restrict__ W2, __half* __restrict__ W2t) {
    __shared__ float tile[32][33];
    const float* src;
    __half* dst;
    int R, C, bx, by;
    int z = blockIdx.z;
    if (z < EE) {            // W1: R=D, C=H
        R = DD; C = HH;
        src = W1 + (size_t)z * R * C;
        dst = W1t + (size_t)z * R * C;
        bx = blockIdx.x; by = blockIdx.y;
    } else {                 // W2: R=H, C=D (swap grid axes)
        R = HH; C = DD;
        src = W2 + (size_t)(z - EE) * R * C;
        dst = W2t + (size_t)(z - EE) * R * C;
        bx = blockIdx.y; by = blockIdx.x;
    }
    int c0 = bx * 32, r0 = by * 32;
    int tx = threadIdx.x, ty = threadIdx.y;
    #pragma unroll
    for (int j = 0; j < 32; j += 8)
        tile[ty + j][tx] = src[(size_t)(r0 + ty + j) * C + c0 + tx];
    __syncthreads();
    #pragma unroll
    for (int j = 0; j < 32; j += 8)
        dst[(size_t)(c0 + ty + j) * R + r0 + tx] = __float2half_rn(tile[tx][ty + j]);
}

// ---------------- fp16 mma.sync GEMM -----------------------------------------
// C[b](TT x ND) = act(A[b](TT x KD) @ Bt[e]^T + bias[e]);  Bt: [E][ND][KD] fp16
// CTA tile 128x256, BK=64 halves (128B rows), 3-stage cp.async, 8 warps 64x64.
// 1 CTA/SM: ILP (32 indep MMA per ldsm batch) hides LDS latency.
template <int KD, int ND, bool RELU, bool OUT_HALF, bool GDS>
__global__ __launch_bounds__(256, 1)
void moe_gemm(const __half* __restrict__ A, const __half* __restrict__ Bt,
              const float* __restrict__ bias, void* __restrict__ Cv) {
    if (GDS) {
        cudaGridDependencySynchronize();
    } else {
        if (threadIdx.x == 0) cudaTriggerProgrammaticLaunchCompletion();
    }
    extern __shared__ uint8_t smraw[];
    const int tid = threadIdx.x, wid = tid >> 5, lane = tid & 31;
    const int b = blockIdx.z;
    const int e = g_expert[b];
    const int row0 = blockIdx.y * 128;
    const int col0 = blockIdx.x * 256;

    const __half* Ab = A + (size_t)b * TT * KD;
    const __half* Bb = Bt + (size_t)e * ND * KD;
    const float* biasb = bias + (size_t)e * ND;

    const uint32_t smBase = smem_u32(smraw);
    const int lr = tid >> 3;   // loader row (0..31)
    const int lc = tid & 7;    // loader 16B chunk (0..7) -> 8 halves

    constexpr int NC = KD / 64;
    constexpr uint32_t STAGE = 49152u;   // 16 KB A + 32 KB B

    auto issue = [&](int c) {
        if (c < NC) {
            uint32_t sA = smBase + (uint32_t)(c % 3) * STAGE;
            uint32_t sB = sA + 16384u;
            int k0 = c * 64;
            #pragma unroll
            for (int i = 0; i < 4; ++i) {               // A: 128 rows
                int r = lr + 32 * i;
                cp_async16(sA + SWZ((uint32_t)(r * 128 + lc * 16)),
                           Ab + (size_t)(row0 + r) * KD + k0 + lc * 8);
            }
            #pragma unroll
            for (int i = 0; i < 8; ++i) {               // B: 256 rows
                int r = lr + 32 * i;
                cp_async16(sB + SWZ((uint32_t)(r * 128 + lc * 16)),
                           Bb + (size_t)(col0 + r) * KD + k0 + lc * 8);
            }
        }
        cp_commit();
    };

    issue(0);
    issue(1);

    const int wm = wid >> 2;   // 0..1  (64-row warp tile)
    const int wn = wid & 3;    // 0..3  (64-col warp tile)

    // ldmatrix lane addressing
    const int aRow = lane & 15;          // A: row within 16-row tile
    const int aColB = (lane >> 4) * 16;  // A: 16B col half (k 0-7 / 8-15)
    const int bRow = ((lane >> 4) & 1) * 8 + (lane & 7);  // B: n row within 16
    const int bColB = ((lane >> 3) & 1) * 16;             // B: k-half bytes

    float acc[4][8][4];
    #pragma unroll
    for (int mt = 0; mt < 4; ++mt)
        #pragma unroll
        for (int nt = 0; nt < 8; ++nt)
            #pragma unroll
            for (int k = 0; k < 4; ++k) acc[mt][nt][k] = 0.f;

    #pragma unroll 1
    for (int c = 0; c < NC; ++c) {
        cp_wait1();
        __syncthreads();
        issue(c + 2);

        uint32_t sA = smBase + (uint32_t)(c % 3) * STAGE;
        uint32_t sB = sA + 16384u;

        #pragma unroll
        for (int ks = 0; ks < 4; ++ks) {        // 4 x k16 per 64-half chunk
            uint32_t af[4][4];
            #pragma unroll
            for (int mt = 0; mt < 4; ++mt) {
                int row = wm * 64 + mt * 16 + aRow;
                ldsm4(af[mt], sA + SWZ((uint32_t)(row * 128 + ks * 32 + aColB)));
            }
            uint32_t bf[4][4];
            #pragma unroll
            for (int np = 0; np < 4; ++np) {    // 4 x 16 n-cols = 64
                int row = wn * 64 + np * 16 + bRow;
                ldsm4(bf[np], sB + SWZ((uint32_t)(row * 128 + ks * 32 + bColB)));
            }
            #pragma unroll
            for (int mt = 0; mt < 4; ++mt)
                #pragma unroll
                for (int nt = 0; nt < 8; ++nt) {
                    const uint32_t* bp = &bf[nt >> 1][(nt & 1) * 2];
                    mma16816(acc[mt][nt], af[mt], bp[0], bp[1]);
                }
        }
    }

    // ---------------- epilogue: bias (+relu) ----------------
    #pragma unroll
    for (int mt = 0; mt < 4; ++mt) {
        #pragma unroll
        for (int nt = 0; nt < 8; ++nt) {
            int col = col0 + wn * 64 + nt * 8 + (lane & 3) * 2;
            float bv0 = __ldg(biasb + col);
            float bv1 = __ldg(biasb + col + 1);
            #pragma unroll
            for (int h = 0; h < 2; ++h) {
                int row = row0 + wm * 64 + mt * 16 + (lane >> 2) + h * 8;
                float v0 = acc[mt][nt][h * 2 + 0] + bv0;
                float v1 = acc[mt][nt][h * 2 + 1] + bv1;
                if (RELU) { v0 = fmaxf(v0, 0.f); v1 = fmaxf(v1, 0.f); }
                if (OUT_HALF) {
                    __half2* Ch = (__half2*)((__half*)Cv + (size_t)b * TT * ND);
                    Ch[((size_t)row * ND + col) / 2] = __floats2half2_rn(v0, v1);
                } else {
                    float2 u; u.x = v0; u.y = v1;
                    *reinterpret_cast<float2*>((float*)Cv + (size_t)b * TT * ND +
                                               (size_t)row * ND + col) = u;
                }
            }
        }
    }
}

// ---------------- launch -----------------------------------------------------
extern "C" void kernel_launch(void* const* d_in, const int* in_sizes, int n_in,
                              void* d_out, int out_size) {
    const float* x  = (const float*)d_in[0];
    const float* Wp = (const float*)d_in[1];
    const float* bp = (const float*)d_in[2];
    const float* W1 = (const float*)d_in[3];
    const float* b1 = (const float*)d_in[4];
    const float* W2 = (const float*)d_in[5];
    const float* b2 = (const float*)d_in[6];
    float* out = (float*)d_out;

    void *pW1t, *pW2t, *pH, *pX, *pPart;
    cudaGetSymbolAddress(&pW1t, g_W1t);
    cudaGetSymbolAddress(&pW2t, g_W2t);
    cudaGetSymbolAddress(&pH, g_h);
    cudaGetSymbolAddress(&pX, g_x);
    cudaGetSymbolAddress(&pPart, g_part);

    const int SMEM = 147456;   // 3 stages x 48 KB
    cudaFuncSetAttribute(moe_gemm<DD, HH, true, true, false>,
                         cudaFuncAttributeMaxDynamicSharedMemorySize, SMEM);
    cudaFuncSetAttribute(moe_gemm<HH, DD, false, false, true>,
                         cudaFuncAttributeMaxDynamicSharedMemorySize, SMEM);
    cudaFuncSetAttribute(moe_gemm<DD, HH, true, true, false>,
                         cudaFuncAttributePreferredSharedMemoryCarveout, 100);
    cudaFuncSetAttribute(moe_gemm<HH, DD, false, false, true>,
                         cudaFuncAttributePreferredSharedMemoryCarveout, 100);

    cudaLaunchAttribute pdl[1];
    pdl[0].id = cudaLaunchAttributeProgrammaticStreamSerialization;
    pdl[0].val.programmaticStreamSerializationAllowed = 1;

    // 1) convert_pool (triggers PDL at start so transposes overlap it)
    convert_pool<<<dim3(BB, 8), 256>>>(x, (__half2*)pX, (float*)pPart);

    // 2) weight transposes (PDL secondary: overlaps convert_pool)
    {
        cudaLaunchConfig_t cfg = {};
        cfg.gridDim = dim3(64, 16, 16);
        cfg.blockDim = dim3(32, 8, 1);
        cfg.attrs = pdl; cfg.numAttrs = 1;
        cudaLaunchKernelEx(&cfg, transpose_both, W1, (__half*)pW1t, W2, (__half*)pW2t);
    }

    // 3) router (normal launch: waits for all priors)
    router_final<<<BB, 256>>>((const float*)pPart, Wp, bp, out + (size_t)BB * TT * DD);

    // 4) GEMM1: h = relu(x @ W1[e] + b1[e]), fp16 out
    moe_gemm<DD, HH, true, true, false>
        <<<dim3(HH / 256, TT / 128, BB), 256, SMEM>>>(
            (const __half*)pX, (const __half*)pW1t, b1, pH);

    // 5) GEMM2: out = h @ W2[e] + b2[e], fp32 out (PDL secondary)
    {
        cudaLaunchConfig_t cfg = {};
        cfg.gridDim = dim3(DD / 256, TT / 128, BB);
        cfg.blockDim = dim3(256, 1, 1);
        cfg.dynamicSmemBytes = SMEM;
        cfg.attrs = pdl; cfg.numAttrs = 1;
        cudaLaunchKernelEx(&cfg, moe_gemm<HH, DD, false, false, true>,
                           (const __half*)pH, (const __half*)pW2t, b2, (void*)out);
    }
}

// round 10
// speedup vs baseline: 1.0812x; 1.0812x over previous
#include <cuda_runtime.h>
#include <cuda_fp16.h>
#include <cstdint>

#define BB 32
#define TT 512
#define DD 512
#define EE 8
#define HH 2048

// ---------------- device scratch (no cudaMalloc allowed) -------------------
__device__ __half g_h[(size_t)BB * TT * HH];      // h (relu'd)   64 MB
__device__ __half g_x[(size_t)BB * TT * DD];      // x as fp16    16 MB
__device__ __half g_W1t[(size_t)EE * HH * DD];    // W1^T fp16 [E][H][D] 16 MB
__device__ __half g_W2t[(size_t)EE * DD * HH];    // W2^T fp16 [E][D][H] 16 MB
__device__ float  g_part[BB * 8 * DD];
__device__ int    g_expert[BB];

// ---------------- helpers ---------------------------------------------------
__device__ __forceinline__ uint32_t smem_u32(const void* p) {
    uint32_t a;
    asm("{ .reg .u64 t; cvta.to.shared.u64 t, %1; cvt.u32.u64 %0, t; }" : "=r"(a) : "l"(p));
    return a;
}
#define SWZ(o) ((o) ^ ((((uint32_t)(o)) >> 3) & 0x70u))

__device__ __forceinline__ void cp_async16(uint32_t dst, const void* src) {
    asm volatile("cp.async.cg.shared.global [%0], [%1], 16;" :: "r"(dst), "l"(src));
}
__device__ __forceinline__ void cp_commit() {
    asm volatile("cp.async.commit_group;" ::: "memory");
}
__device__ __forceinline__ void cp_wait1() {
    asm volatile("cp.async.wait_group 1;" ::: "memory");
}
__device__ __forceinline__ void ldsm4(uint32_t* r, uint32_t addr) {
    asm volatile("ldmatrix.sync.aligned.m8n8.x4.shared.b16 {%0,%1,%2,%3}, [%4];"
                 : "=r"(r[0]), "=r"(r[1]), "=r"(r[2]), "=r"(r[3]) : "r"(addr));
}
__device__ __forceinline__ void mma16816(float* d, const uint32_t* a, uint32_t b0, uint32_t b1) {
    asm volatile("mma.sync.aligned.m16n8k16.row.col.f32.f16.f16.f32 "
                 "{%0,%1,%2,%3}, {%4,%5,%6,%7}, {%8,%9}, {%0,%1,%2,%3};"
                 : "+f"(d[0]), "+f"(d[1]), "+f"(d[2]), "+f"(d[3])
                 : "r"(a[0]), "r"(a[1]), "r"(a[2]), "r"(a[3]), "r"(b0), "r"(b1));
}

// ---------------- router (fused x -> fp16 convert + pooling) ----------------
__global__ void convert_pool(const float* __restrict__ x, __half2* __restrict__ xt,
                             float* __restrict__ part) {
    if (threadIdx.x == 0) cudaTriggerProgrammaticLaunchCompletion();
    int b = blockIdx.x, s = blockIdx.y, tid = threadIdx.x;   // tid: half2 index 0..255
    size_t base = ((size_t)b * TT + s * 64) * DD;
    float s0 = 0.f, s1 = 0.f;
    #pragma unroll 4
    for (int t = 0; t < 64; ++t) {
        float2 v = *reinterpret_cast<const float2*>(x + base + (size_t)t * DD + 2 * tid);
        s0 += v.x; s1 += v.y;
        xt[(base + (size_t)t * DD) / 2 + tid] = __floats2half2_rn(v.x, v.y);
    }
    float2 p; p.x = s0; p.y = s1;
    *reinterpret_cast<float2*>(part + ((size_t)b * 8 + s) * DD + 2 * tid) = p;
}

__global__ void router_final(const float* __restrict__ part,
                             const float* __restrict__ Wp,
                             const float* __restrict__ bp,
                             float* __restrict__ out_tail) {
    int b = blockIdx.x, tid = threadIdx.x;
    __shared__ float pooled[DD];
    __shared__ float logits[EE];

    for (int d = tid; d < DD; d += 256) {
        float s = 0.f;
        #pragma unroll
        for (int p = 0; p < 8; ++p) s += part[((size_t)b * 8 + p) * DD + d];
        pooled[d] = s * (1.0f / TT);
    }
    __syncthreads();

    int warp = tid >> 5, lane = tid & 31;
    if (warp < EE) {
        float s = 0.f;
        for (int d = lane; d < DD; d += 32) s += pooled[d] * Wp[(size_t)d * EE + warp];
        #pragma unroll
        for (int o = 16; o > 0; o >>= 1) s += __shfl_xor_sync(0xffffffffu, s, o);
        if (lane == 0) logits[warp] = s + bp[warp];
    }
    __syncthreads();

    if (tid == 0) {
        float m = logits[0]; int arg = 0;
        #pragma unroll
        for (int e = 1; e < EE; ++e) if (logits[e] > m) { m = logits[e]; arg = e; }
        float p[EE], sum = 0.f;
        #pragma unroll
        for (int e = 0; e < EE; ++e) { p[e] = __expf(logits[e] - m); sum += p[e]; }
        float inv = 1.0f / sum;
        #pragma unroll
        for (int e = 0; e < EE; ++e) out_tail[b * EE + e] = p[e] * inv;
        out_tail[BB * EE + b] = (float)arg;
        g_expert[b] = arg;
    }
}

// ---------------- weight transpose + fp16 rounding ---------------------------
// src: [E][R][C] fp32 -> dst: [E][C][R] fp16. Grid: (C/32, R/32, E).
__global__ void transpose_w(const float* __restrict__ src, __half* __restrict__ dst,
                            int R, int C) {
    __shared__ float tile[32][33];
    int e = blockIdx.z;
    src += (size_t)e * R * C;
    dst += (size_t)e * R * C;
    int c0 = blockIdx.x * 32, r0 = blockIdx.y * 32;
    int tx = threadIdx.x, ty = threadIdx.y;
    #pragma unroll
    for (int j = 0; j < 32; j += 8)
        tile[ty + j][tx] = src[(size_t)(r0 + ty + j) * C + c0 + tx];
    __syncthreads();
    #pragma unroll
    for (int j = 0; j < 32; j += 8)
        dst[(size_t)(c0 + ty + j) * R + r0 + tx] = __float2half_rn(tile[tx][ty + j]);
}

// ---------------- fp16 mma.sync GEMM -----------------------------------------
// C[b](TT x ND) = act(A[b](TT x KD) @ Bt[e]^T + bias[e]);  Bt: [E][ND][KD] fp16
// CTA tile 128x128, BK=64 halves (128B rows), 3-stage cp.async, 8 warps 64x32.
// 2 CTAs/SM (16 warps). TRIG: trigger PDL at block start (lets next launch in).
template <int KD, int ND, bool RELU, bool OUT_HALF, bool TRIG>
__global__ __launch_bounds__(256, 2)
void moe_gemm(const __half* __restrict__ A, const __half* __restrict__ Bt,
              const float* __restrict__ bias, void* __restrict__ Cv) {
    if (TRIG) {
        if (threadIdx.x == 0) cudaTriggerProgrammaticLaunchCompletion();
    }
    extern __shared__ uint8_t smraw[];
    const int tid = threadIdx.x, wid = tid >> 5, lane = tid & 31;
    const int b = blockIdx.z;
    const int e = g_expert[b];
    const int row0 = blockIdx.y * 128;
    const int col0 = blockIdx.x * 128;

    const __half* Ab = A + (size_t)b * TT * KD;
    const __half* Bb = Bt + (size_t)e * ND * KD;
    const float* biasb = bias + (size_t)e * ND;

    const uint32_t smBase = smem_u32(smraw);
    const int lr = tid >> 3;   // loader row (0..31)
    const int lc = tid & 7;    // loader 16B chunk (0..7) -> 8 halves

    constexpr int NC = KD / 64;

    auto issue = [&](int c) {
        if (c < NC) {
            uint32_t sA = smBase + (uint32_t)(c % 3) * 32768u;
            uint32_t sB = sA + 16384u;
            int k0 = c * 64;
            #pragma unroll
            for (int i = 0; i < 4; ++i) {
                int r = lr + 32 * i;
                cp_async16(sA + SWZ((uint32_t)(r * 128 + lc * 16)),
                           Ab + (size_t)(row0 + r) * KD + k0 + lc * 8);
            }
            #pragma unroll
            for (int i = 0; i < 4; ++i) {
                int r = lr + 32 * i;
                cp_async16(sB + SWZ((uint32_t)(r * 128 + lc * 16)),
                           Bb + (size_t)(col0 + r) * KD + k0 + lc * 8);
            }
        }
        cp_commit();
    };

    issue(0);
    issue(1);

    const int wm = wid >> 2;   // 0..1
    const int wn = wid & 3;    // 0..3

    // ldmatrix lane addressing
    const int aRow = lane & 15;          // A: row within 16-row tile
    const int aColB = (lane >> 4) * 16;  // A: 16B col half (k 0-7 / 8-15)
    const int bRow = ((lane >> 4) & 1) * 8 + (lane & 7);  // B: n row within 16
    const int bColB = ((lane >> 3) & 1) * 16;             // B: k-half bytes

    float acc[4][4][4];
    #pragma unroll
    for (int mt = 0; mt < 4; ++mt)
        #pragma unroll
        for (int nt = 0; nt < 4; ++nt)
            #pragma unroll
            for (int k = 0; k < 4; ++k) acc[mt][nt][k] = 0.f;

    #pragma unroll 1
    for (int c = 0; c < NC; ++c) {
        cp_wait1();
        __syncthreads();
        issue(c + 2);

        uint32_t sA = smBase + (uint32_t)(c % 3) * 32768u;
        uint32_t sB = sA + 16384u;

        #pragma unroll
        for (int ks = 0; ks < 4; ++ks) {        // 4 x k16 per 64-half chunk
            uint32_t af[4][4];
            #pragma unroll
            for (int mt = 0; mt < 4; ++mt) {
                int row = wm * 64 + mt * 16 + aRow;
                ldsm4(af[mt], sA + SWZ((uint32_t)(row * 128 + ks * 32 + aColB)));
            }
            uint32_t bf[2][4];
            #pragma unroll
            for (int np = 0; np < 2; ++np) {
                int row = wn * 32 + np * 16 + bRow;
                ldsm4(bf[np], sB + SWZ((uint32_t)(row * 128 + ks * 32 + bColB)));
            }
            #pragma unroll
            for (int mt = 0; mt < 4; ++mt)
                #pragma unroll
                for (int nt = 0; nt < 4; ++nt) {
                    const uint32_t* bp = &bf[nt >> 1][(nt & 1) * 2];
                    mma16816(acc[mt][nt], af[mt], bp[0], bp[1]);
                }
        }
    }

    // ---------------- epilogue: bias (+relu) ----------------
    #pragma unroll
    for (int mt = 0; mt < 4; ++mt) {
        #pragma unroll
        for (int nt = 0; nt < 4; ++nt) {
            int col = col0 + wn * 32 + nt * 8 + (lane & 3) * 2;
            float bv0 = __ldg(biasb + col);
            float bv1 = __ldg(biasb + col + 1);
            #pragma unroll
            for (int h = 0; h < 2; ++h) {
                int row = row0 + wm * 64 + mt * 16 + (lane >> 2) + h * 8;
                float v0 = acc[mt][nt][h * 2 + 0] + bv0;
                float v1 = acc[mt][nt][h * 2 + 1] + bv1;
                if (RELU) { v0 = fmaxf(v0, 0.f); v1 = fmaxf(v1, 0.f); }
                if (OUT_HALF) {
                    __half2* Ch = (__half2*)((__half*)Cv + (size_t)b * TT * ND);
                    Ch[((size_t)row * ND + col) / 2] = __floats2half2_rn(v0, v1);
                } else {
                    float2 u; u.x = v0; u.y = v1;
                    *reinterpret_cast<float2*>((float*)Cv + (size_t)b * TT * ND +
                                               (size_t)row * ND + col) = u;
                }
            }
        }
    }
}

// ---------------- launch -----------------------------------------------------
extern "C" void kernel_launch(void* const* d_in, const int* in_sizes, int n_in,
                              void* d_out, int out_size) {
    const float* x  = (const float*)d_in[0];
    const float* Wp = (const float*)d_in[1];
    const float* bp = (const float*)d_in[2];
    const float* W1 = (const float*)d_in[3];
    const float* b1 = (const float*)d_in[4];
    const float* W2 = (const float*)d_in[5];
    const float* b2 = (const float*)d_in[6];
    float* out = (float*)d_out;

    void *pW1t, *pW2t, *pH, *pX, *pPart;
    cudaGetSymbolAddress(&pW1t, g_W1t);
    cudaGetSymbolAddress(&pW2t, g_W2t);
    cudaGetSymbolAddress(&pH, g_h);
    cudaGetSymbolAddress(&pX, g_x);
    cudaGetSymbolAddress(&pPart, g_part);

    const int SMEM = 98304;
    cudaFuncSetAttribute(moe_gemm<DD, HH, true, true, true>,
                         cudaFuncAttributeMaxDynamicSharedMemorySize, SMEM);
    cudaFuncSetAttribute(moe_gemm<HH, DD, false, false, false>,
                         cudaFuncAttributeMaxDynamicSharedMemorySize, SMEM);
    cudaFuncSetAttribute(moe_gemm<DD, HH, true, true, true>,
                         cudaFuncAttributePreferredSharedMemoryCarveout, 100);
    cudaFuncSetAttribute(moe_gemm<HH, DD, false, false, false>,
                         cudaFuncAttributePreferredSharedMemoryCarveout, 100);

    cudaLaunchAttribute pdl[1];
    pdl[0].id = cudaLaunchAttributeProgrammaticStreamSerialization;
    pdl[0].val.programmaticStreamSerializationAllowed = 1;

    // 1) convert_pool (PDL-triggers at start so trans_W1 overlaps it)
    convert_pool<<<dim3(BB, 8), 256>>>(x, (__half2*)pX, (float*)pPart);

    // 2) W1 transpose only (PDL secondary: overlaps convert_pool)
    {
        cudaLaunchConfig_t cfg = {};
        cfg.gridDim = dim3(HH / 32, DD / 32, EE);   // C=H, R=D
        cfg.blockDim = dim3(32, 8, 1);
        cfg.attrs = pdl; cfg.numAttrs = 1;
        cudaLaunchKernelEx(&cfg, transpose_w, W1, (__half*)pW1t, DD, HH);
    }

    // 3) router (normal: waits convert_pool + trans_W1)
    router_final<<<BB, 256>>>((const float*)pPart, Wp, bp, out + (size_t)BB * TT * DD);

    // 4) GEMM1: h = relu(x @ W1[e] + b1[e])  (PDL-triggers at start)
    moe_gemm<DD, HH, true, true, true>
        <<<dim3(HH / 128, TT / 128, BB), 256, SMEM>>>(
            (const __half*)pX, (const __half*)pW1t, b1, pH);

    // 5) W2 transpose (PDL secondary: runs CONCURRENTLY with tensor-bound GEMM1)
    {
        cudaLaunchConfig_t cfg = {};
        cfg.gridDim = dim3(DD / 32, HH / 32, EE);   // C=D, R=H
        cfg.blockDim = dim3(32, 8, 1);
        cfg.attrs = pdl; cfg.numAttrs = 1;
        cudaLaunchKernelEx(&cfg, transpose_w, W2, (__half*)pW2t, HH, DD);
    }

    // 6) GEMM2: out = h @ W2[e] + b2[e]  (normal: waits GEMM1 + trans_W2)
    moe_gemm<HH, DD, false, false, false>
        <<<dim3(DD / 128, TT / 128, BB), 256, SMEM>>>(
            (const __half*)pH, (const __half*)pW2t, b2, (void*)out);
}